// round 10
// baseline (speedup 1.0000x reference)
#include <cuda_runtime.h>
#include <math.h>

typedef unsigned long long ull;

// ---------------- problem constants ----------------
#define NNODE 200
#define IMGF  2048
#define HD1   512
#define HD2   256
#define NCH   1024
#define NEDGE 39800
#define TE    32

// ---------------- f32x2 helpers ----------------
__device__ __forceinline__ ull pack2(float a) {
    ull r; asm("mov.b64 %0,{%1,%1};" : "=l"(r) : "f"(a)); return r;
}
__device__ __forceinline__ void ffma2(ull& acc, ull a, ull b) {
    asm("fma.rn.f32x2 %0,%1,%2,%0;" : "+l"(acc) : "l"(a), "l"(b));
}
__device__ __forceinline__ float2 unpk(ull v) {
    float2 r; asm("mov.b64 {%0,%1},%2;" : "=f"(r.x), "=f"(r.y) : "l"(v)); return r;
}

// ---------------- PDL helpers ----------------
__device__ __forceinline__ void pdl_trigger() {
#if defined(__CUDA_ARCH__) && __CUDA_ARCH__ >= 900
    cudaTriggerProgrammaticLaunchCompletion();
#endif
}
__device__ __forceinline__ void pdl_wait() {
#if defined(__CUDA_ARCH__) && __CUDA_ARCH__ >= 900
    cudaGridDependencySynchronize();
#endif
}

// ---------------- device scratch ----------------
#define OFF_H1   0
#define OFF_H2   (OFF_H1 + NNODE*HD1)
#define OFF_X    (OFF_H2 + NNODE*HD2)
#define OFF_M    (OFF_X  + NNODE*NCH)
#define ZERO_CNT (OFF_M  + NNODE*512)          // h1,h2,x,M zeroed
#define OFF_P    (ZERO_CNT)
#define OFF_Q    (OFF_P + NNODE*256)
#define OFF_CV   (OFF_Q + NNODE*256)
#define SCR_TOTAL (OFF_CV + NNODE*4)
__device__ float g_scr[SCR_TOTAL];

// ---------------- zero kernel (replaces cudaMemsetAsync node) ----------------
__global__ void k_zero(float* __restrict__ p) {
    pdl_trigger();
    float4 z = make_float4(0.f, 0.f, 0.f, 0.f);
    for (int i = blockIdx.x * 256 + threadIdx.x; i < ZERO_CNT / 4; i += gridDim.x * 256)
        ((float4*)p)[i] = z;
}

// P[n][j] = attr(n) @ we1[0:8]  ;  Q[n][j] = attr(n) @ we1[8:16]
__global__ void k_pq(const float* __restrict__ bbox, const float* __restrict__ dirs,
                     const float* __restrict__ we1,
                     float* __restrict__ P, float* __restrict__ Q) {
    pdl_trigger();
    __shared__ float a[8];
    int n = blockIdx.y, j = blockIdx.x * 128 + threadIdx.x;
    if (threadIdx.x < 8) {
        int c = threadIdx.x;
        a[c] = (c < 4) ? bbox[n * 4 + c] * (1.0f / 1024.0f) : dirs[n * 4 + c - 4];
    }
    __syncthreads();
    float p = 0.f, q = 0.f;
    #pragma unroll
    for (int c = 0; c < 8; ++c) {
        p += a[c] * we1[c * 256 + j];
        q += a[c] * we1[(c + 8) * 256 + j];
    }
    P[n * 256 + j] = p;
    Q[n * 256 + j] = q;
}

// per-node [1024] -> 12 outputs
__global__ void __launch_bounds__(256) k_vec4b(
    const float* __restrict__ x,
    const float* __restrict__ wi, const float* __restrict__ bi,
    const float* __restrict__ bp2,
    const float* __restrict__ rw, const float* __restrict__ rb,
    float* __restrict__ out_expl, float* __restrict__ cvec,
    float* __restrict__ out_agg) {
    pdl_trigger();
    pdl_wait();                                   // x from g3 (stream-transitive)
    int n = blockIdx.x, t = threadIdx.x;
    float4 xv = *(const float4*)(x + (size_t)n * NCH + t * 4);
    float xa[4] = {xv.x, xv.y, xv.z, xv.w};
    float v[12];
    #pragma unroll
    for (int c = 0; c < 12; ++c) v[c] = 0.f;
    #pragma unroll
    for (int j = 0; j < 4; ++j) {
        int i = t * 4 + j;
        float xs = xa[j];
        float4 w0 = *(const float4*)(wi  + i * 4);
        float4 w1 = *(const float4*)(bp2 + i * 4);
        float4 w2 = *(const float4*)(rw  + i * 4);
        v[0] += xs * w0.x; v[1] += xs * w0.y; v[2]  += xs * w0.z; v[3]  += xs * w0.w;
        v[4] += xs * w1.x; v[5] += xs * w1.y; v[6]  += xs * w1.z; v[7]  += xs * w1.w;
        v[8] += xs * w2.x; v[9] += xs * w2.y; v[10] += xs * w2.z; v[11] += xs * w2.w;
    }
    #pragma unroll
    for (int s = 16; s; s >>= 1)
        #pragma unroll
        for (int c = 0; c < 12; ++c) v[c] += __shfl_xor_sync(0xffffffffu, v[c], s);
    __shared__ float red[8][13];
    if ((t & 31) == 0)
        #pragma unroll
        for (int c = 0; c < 12; ++c) red[t >> 5][c] = v[c];
    __syncthreads();
    if (t < 12) {
        float s = 0.f;
        #pragma unroll
        for (int w = 0; w < 8; ++w) s += red[w][t];
        int o = t & 3;
        if (t < 4)       out_expl[n * 4 + o] = 1.f / (1.f + __expf(-(s + bi[o])));
        else if (t < 8)  cvec[n * 4 + o] = s;
        else             out_agg[n * 4 + o] = s + rb[o];
    }
}

// ---------------- split-K SGEMM: atomicAdd(C, A@B), split 0 adds bias --------
// TRB=1: B_t[i][j] = wp2[(j>>2)*4096 + i*4 + (j&3)]
// SYNCW=0: pdl_wait before k-loop (A comes from predecessor)
// SYNCW=1: pdl_wait only before epilogue (C zeroing is the only dependency)
template <int RELU_A, int TRB, int SYNCW>
__global__ void __launch_bounds__(256) sgemm_sk(
    const float* __restrict__ A, const float* __restrict__ B,
    const float* __restrict__ bias, float* __restrict__ C,
    int M, int N, int K, int Ks) {
    pdl_trigger();
    __shared__ float sA[16][36];
    __shared__ float sB[16][132];
    const int tid = threadIdx.x;
    const int tx = tid & 31, ty = tid >> 5;
    const int m0 = blockIdx.y * 32, n0 = blockIdx.x * 128;
    const int kbeg = blockIdx.z * Ks;
    ull acc[8];
    #pragma unroll
    for (int i = 0; i < 8; ++i) acc[i] = 0ULL;

    if (SYNCW == 0) pdl_wait();

    for (int k0 = kbeg; k0 < kbeg + Ks; k0 += 16) {
        {
            int m = tid >> 3, kq = (tid & 7) * 2;
            float2 a = make_float2(0.f, 0.f);
            if (m0 + m < M) a = *(const float2*)(A + (size_t)(m0 + m) * K + k0 + kq);
            if (RELU_A) { a.x = fmaxf(a.x, 0.f); a.y = fmaxf(a.y, 0.f); }
            sA[kq][m] = a.x; sA[kq + 1][m] = a.y;
        }
        if (TRB == 0) {
            int k = tid >> 4, n8 = (tid & 15) * 8;
            const float* bp = B + (size_t)(k0 + k) * N + n0 + n8;
            float4 b0 = *(const float4*)(bp);
            float4 b1 = *(const float4*)(bp + 4);
            *(float4*)&sB[k][n8] = b0;
            *(float4*)&sB[k][n8 + 4] = b1;
        } else {
            int k = tid & 15, n8 = (tid >> 4) * 8;
            int i = k0 + k, j0 = n0 + n8;
            const float* bp = B + (size_t)(j0 >> 2) * 4096 + i * 4;
            float4 b0 = *(const float4*)(bp);
            float4 b1 = *(const float4*)(bp + 4096);
            *(float4*)&sB[k][n8] = b0;
            *(float4*)&sB[k][n8 + 4] = b1;
        }
        __syncthreads();
        #pragma unroll
        for (int k = 0; k < 16; ++k) {
            float4 av = *(const float4*)&sA[k][ty * 4];
            ulonglong2 bv = *(const ulonglong2*)&sB[k][tx * 4];
            ull a0 = pack2(av.x), a1 = pack2(av.y), a2 = pack2(av.z), a3 = pack2(av.w);
            ffma2(acc[0], a0, bv.x); ffma2(acc[1], a0, bv.y);
            ffma2(acc[2], a1, bv.x); ffma2(acc[3], a1, bv.y);
            ffma2(acc[4], a2, bv.x); ffma2(acc[5], a2, bv.y);
            ffma2(acc[6], a3, bv.x); ffma2(acc[7], a3, bv.y);
        }
        __syncthreads();
    }

    if (SYNCW == 1) pdl_wait();

    const bool addb = (bias != nullptr) && (blockIdx.z == 0);
    #pragma unroll
    for (int r = 0; r < 4; ++r) {
        int row = m0 + ty * 4 + r;
        if (row >= M) continue;
        float2 v01 = unpk(acc[r * 2]), v23 = unpk(acc[r * 2 + 1]);
        float v[4] = {v01.x, v01.y, v23.x, v23.y};
        int col = n0 + tx * 4;
        #pragma unroll
        for (int j = 0; j < 4; ++j) {
            float o = v[j];
            if (addb) o += bias[col + j];
            atomicAdd(&C[(size_t)row * N + col + j], o);
        }
    }
}

// ---------------- edge MLP (L1 gather-add, L2, L3) ----------------
__global__ void __launch_bounds__(128) k_edge_mlp(
    const float* __restrict__ P, const float* __restrict__ Q,
    const float* __restrict__ pri,
    const float* __restrict__ be1,
    const float* __restrict__ we2, const float* __restrict__ be2,
    const float* __restrict__ we3, const float* __restrict__ be3,
    float* __restrict__ out_ea) {
    pdl_trigger();
    __shared__ float s_big[TE * 264];
    __shared__ float s_h2[TE][68];
    __shared__ float s_ea[TE][4];
    __shared__ int s_src[TE], s_dst[TE];

    const int t = threadIdx.x;
    const int e0 = blockIdx.x * TE;

    if (t < TE) {
        int e = e0 + t;
        if (e >= NEDGE) e = NEDGE - 1;
        int i = e / 199;
        int r = e - i * 199;
        int j = (r < i) ? r : (r + 1);
        s_src[t] = i; s_dst[t] = j;
    }
    pdl_wait();                                  // P/Q from k_pq
    __syncthreads();

    // phase 1: h1 = relu(P[src] + Q[dst] + be1)
    #pragma unroll
    for (int l = 0; l < 16; ++l) {
        int idx = l * 128 + t;
        int el = idx >> 6, j4 = idx & 63;
        float4 p = ((const float4*)(P + s_src[el] * 256))[j4];
        float4 q = ((const float4*)(Q + s_dst[el] * 256))[j4];
        float4 b = ((const float4*)be1)[j4];
        float4 o;
        o.x = fmaxf(p.x + q.x + b.x, 0.f);
        o.y = fmaxf(p.y + q.y + b.y, 0.f);
        o.z = fmaxf(p.z + q.z + b.z, 0.f);
        o.w = fmaxf(p.w + q.w + b.w, 0.f);
        *(float4*)&s_big[el * 264 + j4 * 4] = o;
    }
    __syncthreads();

    const int eg = t >> 4, cg = t & 15;

    // phase 2: L2 256->64 (f32x2), 2 k's per step
    {
        ull acc01[4], acc23[4];
        #pragma unroll
        for (int e = 0; e < 4; ++e) { acc01[e] = 0ULL; acc23[e] = 0ULL; }
        #pragma unroll 4
        for (int k = 0; k < 256; k += 2) {
            float2 a0 = *(const float2*)&s_big[(eg * 4 + 0) * 264 + k];
            float2 a1 = *(const float2*)&s_big[(eg * 4 + 1) * 264 + k];
            float2 a2 = *(const float2*)&s_big[(eg * 4 + 2) * 264 + k];
            float2 a3 = *(const float2*)&s_big[(eg * 4 + 3) * 264 + k];
            ulonglong2 b0 = *(const ulonglong2*)(we2 + (k + 0) * 64 + cg * 4);
            ulonglong2 b1 = *(const ulonglong2*)(we2 + (k + 1) * 64 + cg * 4);
            ull p;
            p = pack2(a0.x); ffma2(acc01[0], p, b0.x); ffma2(acc23[0], p, b0.y);
            p = pack2(a1.x); ffma2(acc01[1], p, b0.x); ffma2(acc23[1], p, b0.y);
            p = pack2(a2.x); ffma2(acc01[2], p, b0.x); ffma2(acc23[2], p, b0.y);
            p = pack2(a3.x); ffma2(acc01[3], p, b0.x); ffma2(acc23[3], p, b0.y);
            p = pack2(a0.y); ffma2(acc01[0], p, b1.x); ffma2(acc23[0], p, b1.y);
            p = pack2(a1.y); ffma2(acc01[1], p, b1.x); ffma2(acc23[1], p, b1.y);
            p = pack2(a2.y); ffma2(acc01[2], p, b1.x); ffma2(acc23[2], p, b1.y);
            p = pack2(a3.y); ffma2(acc01[3], p, b1.x); ffma2(acc23[3], p, b1.y);
        }
        #pragma unroll
        for (int e = 0; e < 4; ++e) {
            float2 u0 = unpk(acc01[e]), u1 = unpk(acc23[e]);
            s_h2[eg * 4 + e][cg * 4 + 0] = fmaxf(u0.x + be2[cg * 4 + 0], 0.f);
            s_h2[eg * 4 + e][cg * 4 + 1] = fmaxf(u0.y + be2[cg * 4 + 1], 0.f);
            s_h2[eg * 4 + e][cg * 4 + 2] = fmaxf(u1.x + be2[cg * 4 + 2], 0.f);
            s_h2[eg * 4 + e][cg * 4 + 3] = fmaxf(u1.y + be2[cg * 4 + 3], 0.f);
        }
    }
    __syncthreads();

    // phase 3: L3 64->3 + sigmoid + priority bit
    if (t < 96) {
        int e = t / 3, c = t - (t / 3) * 3;
        float s = be3[c];
        #pragma unroll 8
        for (int k = 0; k < 64; ++k) s += s_h2[e][k] * we3[k * 3 + c];
        s_ea[e][c] = 1.f / (1.f + __expf(-s));
    }
    if (t < TE) s_ea[t][3] = (pri[s_src[t]] > pri[s_dst[t]]) ? 1.f : 0.f;
    __syncthreads();

    {
        int e = t >> 2, c = t & 3;
        if (e0 + e < NEDGE) out_ea[(size_t)(e0 + e) * 4 + c] = s_ea[e][c];
    }
}

// ---------------- message kernel: one block per src node ----------------
__global__ void __launch_bounds__(256) k_msg(
    const float* __restrict__ ea, const float* __restrict__ Mn,
    const float* __restrict__ cvec,
    const float* __restrict__ wp1, const float* __restrict__ bp1,
    float* __restrict__ out_agg) {
    __shared__ float sM[512];
    __shared__ float swp[512];
    __shared__ float sbp[128];
    const int src = blockIdx.x, t = threadIdx.x;
    pdl_wait();                                  // M/cvec from stream 0 chain
    sM[t] = Mn[src * 512 + t];
    sM[t + 256] = Mn[src * 512 + 256 + t];
    swp[t] = wp1[t]; swp[t + 256] = wp1[t + 256];
    if (t < 128) sbp[t] = bp1[t];
    __syncthreads();

    float4 cv = *(const float4*)(cvec + src * 4);
    const int slot = t >> 2, q = t & 3;
    for (int eb = 0; eb < 4; ++eb) {
        int el = eb * 64 + slot;
        if (el >= 199) break;
        int dst = el + (el >= src ? 1 : 0);
        int e = src * 199 + el;
        float4 eav = ((const float4*)ea)[e];
        float4 a = make_float4(0.f, 0.f, 0.f, 0.f);
        #pragma unroll 8
        for (int kk = 0; kk < 32; ++kk) {
            int k = kk * 4 + q;
            float h = sbp[k] + eav.x * swp[k] + eav.y * swp[128 + k]
                             + eav.z * swp[256 + k] + eav.w * swp[384 + k];
            h = fmaxf(h, 0.f);
            float4 m = ((const float4*)sM)[k];
            a.x += h * m.x; a.y += h * m.y; a.z += h * m.z; a.w += h * m.w;
        }
        #pragma unroll
        for (int s = 1; s < 4; s <<= 1) {
            a.x += __shfl_xor_sync(0xffffffffu, a.x, s);
            a.y += __shfl_xor_sync(0xffffffffu, a.y, s);
            a.z += __shfl_xor_sync(0xffffffffu, a.z, s);
            a.w += __shfl_xor_sync(0xffffffffu, a.w, s);
        }
        if (q == 0) {
            atomicAdd(&out_agg[dst * 4 + 0], a.x + cv.x);
            atomicAdd(&out_agg[dst * 4 + 1], a.y + cv.y);
            atomicAdd(&out_agg[dst * 4 + 2], a.z + cv.z);
            atomicAdd(&out_agg[dst * 4 + 3], a.w + cv.w);
        }
    }
}

// ---------------- PDL launch helper ----------------
template <typename F, typename... Args>
static inline void launch_pdl(F kern, dim3 g, dim3 b, cudaStream_t s, Args... args) {
    cudaLaunchConfig_t cfg = {};
    cfg.gridDim = g; cfg.blockDim = b; cfg.dynamicSmemBytes = 0; cfg.stream = s;
    cudaLaunchAttribute at[1];
    at[0].id = cudaLaunchAttributeProgrammaticStreamSerialization;
    at[0].val.programmaticStreamSerializationAllowed = 1;
    cfg.attrs = at; cfg.numAttrs = 1;
    cudaLaunchKernelEx(&cfg, kern, args...);
}

// ---------------- launch ----------------
extern "C" void kernel_launch(void* const* d_in, const int* in_sizes, int n_in,
                              void* d_out, int out_size) {
    const float* roi  = (const float*)d_in[0];
    const float* bbox = (const float*)d_in[1];
    const float* dir  = (const float*)d_in[2];
    const float* pri  = (const float*)d_in[3];
    const float* w1  = (const float*)d_in[4];  const float* b1  = (const float*)d_in[5];
    const float* w2  = (const float*)d_in[6];  const float* b2  = (const float*)d_in[7];
    const float* w3  = (const float*)d_in[8];  const float* b3  = (const float*)d_in[9];
    const float* wi  = (const float*)d_in[10]; const float* bi  = (const float*)d_in[11];
    const float* we1 = (const float*)d_in[12]; const float* be1 = (const float*)d_in[13];
    const float* we2 = (const float*)d_in[14]; const float* be2 = (const float*)d_in[15];
    const float* we3 = (const float*)d_in[16]; const float* be3 = (const float*)d_in[17];
    const float* wp1 = (const float*)d_in[18]; const float* bp1 = (const float*)d_in[19];
    const float* wp2 = (const float*)d_in[20]; const float* bp2 = (const float*)d_in[21];
    const float* rw  = (const float*)d_in[22]; const float* rb  = (const float*)d_in[23];
    float* out = (float*)d_out;

    float* scr;
    cudaGetSymbolAddress((void**)&scr, g_scr);
    float* p_h1 = scr + OFF_H1;
    float* p_h2 = scr + OFF_H2;
    float* p_x  = scr + OFF_X;
    float* p_M  = scr + OFF_M;
    float* p_P  = scr + OFF_P;
    float* p_Q  = scr + OFF_Q;
    float* p_cv = scr + OFF_CV;

    static cudaStream_t s2 = nullptr;
    static cudaEvent_t evF = nullptr, ev2 = nullptr;
    if (!s2) {
        cudaStreamCreateWithFlags(&s2, cudaStreamNonBlocking);
        cudaEventCreateWithFlags(&evF, cudaEventDisableTiming);
        cudaEventCreateWithFlags(&ev2, cudaEventDisableTiming);
    }

    // fork edge branch
    cudaEventRecord(evF, 0);
    cudaStreamWaitEvent(s2, evF, 0);
    k_pq<<<dim3(2, NNODE), 128, 0, s2>>>(bbox, dir, we1, p_P, p_Q);
    launch_pdl(k_edge_mlp, dim3((NEDGE + TE - 1) / TE), dim3(128), s2,
               (const float*)p_P, (const float*)p_Q, pri, be1,
               we2, be2, we3, be3, (float*)(out + 1600));
    cudaEventRecord(ev2, s2);

    // main chain (stream 0) with PDL overlap
    k_zero<<<148, 256, 0, 0>>>(scr);
    // g1: compute overlaps k_zero entirely; sync only before atomic epilogue
    launch_pdl(sgemm_sk<0, 0, 1>, dim3(4, 7, 8), dim3(256), (cudaStream_t)0,
               roi, w1, b1, (float*)p_h1, NNODE, HD1, IMGF, 256);
    launch_pdl(sgemm_sk<1, 0, 0>, dim3(2, 7, 8), dim3(256), (cudaStream_t)0,
               (const float*)p_h1, w2, b2, (float*)p_h2, NNODE, HD2, HD1, 64);
    launch_pdl(sgemm_sk<1, 0, 0>, dim3(8, 7, 4), dim3(256), (cudaStream_t)0,
               (const float*)p_h2, w3, b3, (float*)p_x, NNODE, NCH, HD2, 64);
    launch_pdl(sgemm_sk<0, 1, 0>, dim3(4, 7, 8), dim3(256), (cudaStream_t)0,
               (const float*)p_x, wp2, (const float*)nullptr, (float*)p_M,
               NNODE, 512, NCH, 128);
    launch_pdl(k_vec4b, dim3(NNODE), dim3(256), (cudaStream_t)0,
               (const float*)p_x, wi, bi, bp2, rw, rb,
               (float*)(out + 800), (float*)p_cv, (float*)out);

    // join: message passing + scatter
    cudaStreamWaitEvent(0, ev2, 0);
    launch_pdl(k_msg, dim3(NNODE), dim3(256), (cudaStream_t)0,
               (const float*)(out + 1600), (const float*)p_M, (const float*)p_cv,
               wp1, bp1, (float*)out);
}

// round 11
// speedup vs baseline: 1.1193x; 1.1193x over previous
#include <cuda_runtime.h>
#include <math.h>

typedef unsigned long long ull;

// ---------------- problem constants ----------------
#define NNODE 200
#define IMGF  2048
#define HD1   512
#define HD2   256
#define NCH   1024
#define NEDGE 39800
#define TE    32

// ---------------- f32x2 helpers ----------------
__device__ __forceinline__ ull pack2(float a) {
    ull r; asm("mov.b64 %0,{%1,%1};" : "=l"(r) : "f"(a)); return r;
}
__device__ __forceinline__ void ffma2(ull& acc, ull a, ull b) {
    asm("fma.rn.f32x2 %0,%1,%2,%0;" : "+l"(acc) : "l"(a), "l"(b));
}
__device__ __forceinline__ float2 unpk(ull v) {
    float2 r; asm("mov.b64 {%0,%1},%2;" : "=f"(r.x), "=f"(r.y) : "l"(v)); return r;
}

// ---------------- device scratch ----------------
// h1,h2,x,M receive atomicAdds and are re-zeroed by k_msgvec at the END of
// every execution (CUDA zero-inits device globals, so execution #1 is covered;
// the invariant holds inductively across graph replays).
#define OFF_H1   0
#define OFF_H2   (OFF_H1 + NNODE*HD1)          // 102400
#define OFF_X    (OFF_H2 + NNODE*HD2)          // 153600
#define OFF_M    (OFF_X  + NNODE*NCH)          // 358400
#define OFF_P    (OFF_M  + NNODE*512)
#define OFF_Q    (OFF_P + NNODE*256)
#define SCR_TOTAL (OFF_Q + NNODE*256)
__device__ float g_scr[SCR_TOTAL];

// P[n][j] = attr(n) @ we1[0:8]  ;  Q[n][j] = attr(n) @ we1[8:16]
__global__ void k_pq(const float* __restrict__ bbox, const float* __restrict__ dirs,
                     const float* __restrict__ we1,
                     float* __restrict__ P, float* __restrict__ Q) {
    __shared__ float a[8];
    int n = blockIdx.y, j = blockIdx.x * 128 + threadIdx.x;
    if (threadIdx.x < 8) {
        int c = threadIdx.x;
        a[c] = (c < 4) ? bbox[n * 4 + c] * (1.0f / 1024.0f) : dirs[n * 4 + c - 4];
    }
    __syncthreads();
    float p = 0.f, q = 0.f;
    #pragma unroll
    for (int c = 0; c < 8; ++c) {
        p += a[c] * we1[c * 256 + j];
        q += a[c] * we1[(c + 8) * 256 + j];
    }
    P[n * 256 + j] = p;
    Q[n * 256 + j] = q;
}

// ---------------- split-K SGEMM: atomicAdd(C, A@B), split 0 adds bias --------
// TRB=1: B_t[i][j] = wp2[(j>>2)*4096 + i*4 + (j&3)]
// zout != nullptr: blocks (by==0,bz==0) zero zout[0..800) (ordering for k_msgvec)
template <int RELU_A, int TRB>
__global__ void __launch_bounds__(256) sgemm_sk(
    const float* __restrict__ A, const float* __restrict__ B,
    const float* __restrict__ bias, float* __restrict__ C,
    int M, int N, int K, int Ks, float* __restrict__ zout) {
    __shared__ float sA[16][36];
    __shared__ float sB[16][132];
    const int tid = threadIdx.x;
    const int tx = tid & 31, ty = tid >> 5;
    const int m0 = blockIdx.y * 32, n0 = blockIdx.x * 128;
    const int kbeg = blockIdx.z * Ks;

    if (zout != nullptr && blockIdx.y == 0 && blockIdx.z == 0) {
        int idx = blockIdx.x * 256 + tid;
        if (idx < 2 * NNODE * 4) zout[idx] = 0.f;   // out[0..800)
    }

    ull acc[8];
    #pragma unroll
    for (int i = 0; i < 8; ++i) acc[i] = 0ULL;

    for (int k0 = kbeg; k0 < kbeg + Ks; k0 += 16) {
        {
            int m = tid >> 3, kq = (tid & 7) * 2;
            float2 a = make_float2(0.f, 0.f);
            if (m0 + m < M) a = *(const float2*)(A + (size_t)(m0 + m) * K + k0 + kq);
            if (RELU_A) { a.x = fmaxf(a.x, 0.f); a.y = fmaxf(a.y, 0.f); }
            sA[kq][m] = a.x; sA[kq + 1][m] = a.y;
        }
        if (TRB == 0) {
            int k = tid >> 4, n8 = (tid & 15) * 8;
            const float* bp = B + (size_t)(k0 + k) * N + n0 + n8;
            float4 b0 = *(const float4*)(bp);
            float4 b1 = *(const float4*)(bp + 4);
            *(float4*)&sB[k][n8] = b0;
            *(float4*)&sB[k][n8 + 4] = b1;
        } else {
            int k = tid & 15, n8 = (tid >> 4) * 8;
            int i = k0 + k, j0 = n0 + n8;
            const float* bp = B + (size_t)(j0 >> 2) * 4096 + i * 4;
            float4 b0 = *(const float4*)(bp);
            float4 b1 = *(const float4*)(bp + 4096);
            *(float4*)&sB[k][n8] = b0;
            *(float4*)&sB[k][n8 + 4] = b1;
        }
        __syncthreads();
        #pragma unroll
        for (int k = 0; k < 16; ++k) {
            float4 av = *(const float4*)&sA[k][ty * 4];
            ulonglong2 bv = *(const ulonglong2*)&sB[k][tx * 4];
            ull a0 = pack2(av.x), a1 = pack2(av.y), a2 = pack2(av.z), a3 = pack2(av.w);
            ffma2(acc[0], a0, bv.x); ffma2(acc[1], a0, bv.y);
            ffma2(acc[2], a1, bv.x); ffma2(acc[3], a1, bv.y);
            ffma2(acc[4], a2, bv.x); ffma2(acc[5], a2, bv.y);
            ffma2(acc[6], a3, bv.x); ffma2(acc[7], a3, bv.y);
        }
        __syncthreads();
    }
    const bool addb = (bias != nullptr) && (blockIdx.z == 0);
    #pragma unroll
    for (int r = 0; r < 4; ++r) {
        int row = m0 + ty * 4 + r;
        if (row >= M) continue;
        float2 v01 = unpk(acc[r * 2]), v23 = unpk(acc[r * 2 + 1]);
        float v[4] = {v01.x, v01.y, v23.x, v23.y};
        int col = n0 + tx * 4;
        #pragma unroll
        for (int j = 0; j < 4; ++j) {
            float o = v[j];
            if (addb) o += bias[col + j];
            atomicAdd(&C[(size_t)row * N + col + j], o);
        }
    }
}

// ---------------- edge MLP (L1 gather-add, L2, L3) ----------------
__global__ void __launch_bounds__(128) k_edge_mlp(
    const float* __restrict__ P, const float* __restrict__ Q,
    const float* __restrict__ pri,
    const float* __restrict__ be1,
    const float* __restrict__ we2, const float* __restrict__ be2,
    const float* __restrict__ we3, const float* __restrict__ be3,
    float* __restrict__ out_ea) {
    __shared__ float s_big[TE * 264];
    __shared__ float s_h2[TE][68];
    __shared__ float s_ea[TE][4];
    __shared__ int s_src[TE], s_dst[TE];

    const int t = threadIdx.x;
    const int e0 = blockIdx.x * TE;

    if (t < TE) {
        int e = e0 + t;
        if (e >= NEDGE) e = NEDGE - 1;
        int i = e / 199;
        int r = e - i * 199;
        int j = (r < i) ? r : (r + 1);
        s_src[t] = i; s_dst[t] = j;
    }
    __syncthreads();

    #pragma unroll
    for (int l = 0; l < 16; ++l) {
        int idx = l * 128 + t;
        int el = idx >> 6, j4 = idx & 63;
        float4 p = ((const float4*)(P + s_src[el] * 256))[j4];
        float4 q = ((const float4*)(Q + s_dst[el] * 256))[j4];
        float4 b = ((const float4*)be1)[j4];
        float4 o;
        o.x = fmaxf(p.x + q.x + b.x, 0.f);
        o.y = fmaxf(p.y + q.y + b.y, 0.f);
        o.z = fmaxf(p.z + q.z + b.z, 0.f);
        o.w = fmaxf(p.w + q.w + b.w, 0.f);
        *(float4*)&s_big[el * 264 + j4 * 4] = o;
    }
    __syncthreads();

    const int eg = t >> 4, cg = t & 15;

    {
        ull acc01[4], acc23[4];
        #pragma unroll
        for (int e = 0; e < 4; ++e) { acc01[e] = 0ULL; acc23[e] = 0ULL; }
        #pragma unroll 4
        for (int k = 0; k < 256; k += 2) {
            float2 a0 = *(const float2*)&s_big[(eg * 4 + 0) * 264 + k];
            float2 a1 = *(const float2*)&s_big[(eg * 4 + 1) * 264 + k];
            float2 a2 = *(const float2*)&s_big[(eg * 4 + 2) * 264 + k];
            float2 a3 = *(const float2*)&s_big[(eg * 4 + 3) * 264 + k];
            ulonglong2 b0 = *(const ulonglong2*)(we2 + (k + 0) * 64 + cg * 4);
            ulonglong2 b1 = *(const ulonglong2*)(we2 + (k + 1) * 64 + cg * 4);
            ull p;
            p = pack2(a0.x); ffma2(acc01[0], p, b0.x); ffma2(acc23[0], p, b0.y);
            p = pack2(a1.x); ffma2(acc01[1], p, b0.x); ffma2(acc23[1], p, b0.y);
            p = pack2(a2.x); ffma2(acc01[2], p, b0.x); ffma2(acc23[2], p, b0.y);
            p = pack2(a3.x); ffma2(acc01[3], p, b0.x); ffma2(acc23[3], p, b0.y);
            p = pack2(a0.y); ffma2(acc01[0], p, b1.x); ffma2(acc23[0], p, b1.y);
            p = pack2(a1.y); ffma2(acc01[1], p, b1.x); ffma2(acc23[1], p, b1.y);
            p = pack2(a2.y); ffma2(acc01[2], p, b1.x); ffma2(acc23[2], p, b1.y);
            p = pack2(a3.y); ffma2(acc01[3], p, b1.x); ffma2(acc23[3], p, b1.y);
        }
        #pragma unroll
        for (int e = 0; e < 4; ++e) {
            float2 u0 = unpk(acc01[e]), u1 = unpk(acc23[e]);
            s_h2[eg * 4 + e][cg * 4 + 0] = fmaxf(u0.x + be2[cg * 4 + 0], 0.f);
            s_h2[eg * 4 + e][cg * 4 + 1] = fmaxf(u0.y + be2[cg * 4 + 1], 0.f);
            s_h2[eg * 4 + e][cg * 4 + 2] = fmaxf(u1.x + be2[cg * 4 + 2], 0.f);
            s_h2[eg * 4 + e][cg * 4 + 3] = fmaxf(u1.y + be2[cg * 4 + 3], 0.f);
        }
    }
    __syncthreads();

    if (t < 96) {
        int e = t / 3, c = t - (t / 3) * 3;
        float s = be3[c];
        #pragma unroll 8
        for (int k = 0; k < 64; ++k) s += s_h2[e][k] * we3[k * 3 + c];
        s_ea[e][c] = 1.f / (1.f + __expf(-s));
    }
    if (t < TE) s_ea[t][3] = (pri[s_src[t]] > pri[s_dst[t]]) ? 1.f : 0.f;
    __syncthreads();

    {
        int e = t >> 2, c = t & 3;
        if (e0 + e < NEDGE) out_ea[(size_t)(e0 + e) * 4 + c] = s_ea[e][c];
    }
}

// -------- merged msg + vec + scratch-rezero: one block per src node ----------
__global__ void __launch_bounds__(256) k_msgvec(
    const float* __restrict__ ea, float* __restrict__ Mn,
    float* __restrict__ x, float* __restrict__ h12,
    const float* __restrict__ wi, const float* __restrict__ bi,
    const float* __restrict__ bp2,
    const float* __restrict__ rw, const float* __restrict__ rb,
    const float* __restrict__ wp1, const float* __restrict__ bp1,
    float* __restrict__ out_expl, float* __restrict__ out_agg) {
    __shared__ float sM[512];
    __shared__ float swp[512];
    __shared__ float sbp[128];
    __shared__ float red[8][13];
    __shared__ float s_cv[4];
    const int src = blockIdx.x, t = threadIdx.x;
    const float4 z4 = make_float4(0.f, 0.f, 0.f, 0.f);

    // load M[src] into smem, then zero own slice (consumed)
    sM[t] = Mn[src * 512 + t];
    sM[t + 256] = Mn[src * 512 + 256 + t];
    Mn[src * 512 + t] = 0.f;
    Mn[src * 512 + 256 + t] = 0.f;
    swp[t] = wp1[t]; swp[t + 256] = wp1[t + 256];
    if (t < 128) sbp[t] = bp1[t];

    // vec part: read x[src] (then zero it), 12 reductions
    float4 xv = *(const float4*)(x + (size_t)src * NCH + t * 4);
    *(float4*)(x + (size_t)src * NCH + t * 4) = z4;
    {
        float xa[4] = {xv.x, xv.y, xv.z, xv.w};
        float v[12];
        #pragma unroll
        for (int c = 0; c < 12; ++c) v[c] = 0.f;
        #pragma unroll
        for (int j = 0; j < 4; ++j) {
            int i = t * 4 + j;
            float xs = xa[j];
            float4 w0 = *(const float4*)(wi  + i * 4);
            float4 w1 = *(const float4*)(bp2 + i * 4);
            float4 w2 = *(const float4*)(rw  + i * 4);
            v[0] += xs * w0.x; v[1] += xs * w0.y; v[2]  += xs * w0.z; v[3]  += xs * w0.w;
            v[4] += xs * w1.x; v[5] += xs * w1.y; v[6]  += xs * w1.z; v[7]  += xs * w1.w;
            v[8] += xs * w2.x; v[9] += xs * w2.y; v[10] += xs * w2.z; v[11] += xs * w2.w;
        }
        #pragma unroll
        for (int s = 16; s; s >>= 1)
            #pragma unroll
            for (int c = 0; c < 12; ++c) v[c] += __shfl_xor_sync(0xffffffffu, v[c], s);
        if ((t & 31) == 0)
            #pragma unroll
            for (int c = 0; c < 12; ++c) red[t >> 5][c] = v[c];
    }
    // zero dead h1+h2 slice: 153600 floats / 200 blocks = 192 float4 per block
    if (t < 192) ((float4*)h12)[src * 192 + t] = z4;
    __syncthreads();
    if (t < 12) {
        float s = 0.f;
        #pragma unroll
        for (int w = 0; w < 8; ++w) s += red[w][t];
        int o = t & 3;
        if (t < 4)      out_expl[src * 4 + o] = 1.f / (1.f + __expf(-(s + bi[o])));
        else if (t < 8) s_cv[o] = s;
        else            atomicAdd(&out_agg[src * 4 + o], s + rb[o]);  // root base
    }
    __syncthreads();

    float4 cv = *(const float4*)s_cv;
    const int slot = t >> 2, q = t & 3;
    for (int eb = 0; eb < 4; ++eb) {
        int el = eb * 64 + slot;
        if (el >= 199) break;
        int dst = el + (el >= src ? 1 : 0);
        int e = src * 199 + el;
        float4 eav = ((const float4*)ea)[e];
        float4 a = make_float4(0.f, 0.f, 0.f, 0.f);
        #pragma unroll 8
        for (int kk = 0; kk < 32; ++kk) {
            int k = kk * 4 + q;
            float h = sbp[k] + eav.x * swp[k] + eav.y * swp[128 + k]
                             + eav.z * swp[256 + k] + eav.w * swp[384 + k];
            h = fmaxf(h, 0.f);
            float4 m = ((const float4*)sM)[k];
            a.x += h * m.x; a.y += h * m.y; a.z += h * m.z; a.w += h * m.w;
        }
        #pragma unroll
        for (int s = 1; s < 4; s <<= 1) {
            a.x += __shfl_xor_sync(0xffffffffu, a.x, s);
            a.y += __shfl_xor_sync(0xffffffffu, a.y, s);
            a.z += __shfl_xor_sync(0xffffffffu, a.z, s);
            a.w += __shfl_xor_sync(0xffffffffu, a.w, s);
        }
        if (q == 0) {
            atomicAdd(&out_agg[dst * 4 + 0], a.x + cv.x);
            atomicAdd(&out_agg[dst * 4 + 1], a.y + cv.y);
            atomicAdd(&out_agg[dst * 4 + 2], a.z + cv.z);
            atomicAdd(&out_agg[dst * 4 + 3], a.w + cv.w);
        }
    }
}

// ---------------- launch ----------------
extern "C" void kernel_launch(void* const* d_in, const int* in_sizes, int n_in,
                              void* d_out, int out_size) {
    const float* roi  = (const float*)d_in[0];
    const float* bbox = (const float*)d_in[1];
    const float* dir  = (const float*)d_in[2];
    const float* pri  = (const float*)d_in[3];
    const float* w1  = (const float*)d_in[4];  const float* b1  = (const float*)d_in[5];
    const float* w2  = (const float*)d_in[6];  const float* b2  = (const float*)d_in[7];
    const float* w3  = (const float*)d_in[8];  const float* b3  = (const float*)d_in[9];
    const float* wi  = (const float*)d_in[10]; const float* bi  = (const float*)d_in[11];
    const float* we1 = (const float*)d_in[12]; const float* be1 = (const float*)d_in[13];
    const float* we2 = (const float*)d_in[14]; const float* be2 = (const float*)d_in[15];
    const float* we3 = (const float*)d_in[16]; const float* be3 = (const float*)d_in[17];
    const float* wp1 = (const float*)d_in[18]; const float* bp1 = (const float*)d_in[19];
    const float* wp2 = (const float*)d_in[20]; const float* bp2 = (const float*)d_in[21];
    const float* rw  = (const float*)d_in[22]; const float* rb  = (const float*)d_in[23];
    float* out = (float*)d_out;

    float* scr;
    cudaGetSymbolAddress((void**)&scr, g_scr);
    float* p_h1 = scr + OFF_H1;
    float* p_h2 = scr + OFF_H2;
    float* p_x  = scr + OFF_X;
    float* p_M  = scr + OFF_M;
    float* p_P  = scr + OFF_P;
    float* p_Q  = scr + OFF_Q;

    static cudaStream_t s2 = nullptr;
    static cudaEvent_t evF = nullptr, ev2 = nullptr;
    if (!s2) {
        cudaStreamCreateWithFlags(&s2, cudaStreamNonBlocking);
        cudaEventCreateWithFlags(&evF, cudaEventDisableTiming);
        cudaEventCreateWithFlags(&ev2, cudaEventDisableTiming);
    }

    // fork edge branch
    cudaEventRecord(evF, 0);
    cudaStreamWaitEvent(s2, evF, 0);
    k_pq<<<dim3(2, NNODE), 128, 0, s2>>>(bbox, dir, we1, p_P, p_Q);
    k_edge_mlp<<<(NEDGE + TE - 1) / TE, 128, 0, s2>>>(p_P, p_Q, pri, be1,
                                                      we2, be2, we3, be3,
                                                      out + 1600);
    cudaEventRecord(ev2, s2);

    // main chain (stream 0): scratch pre-zeroed by previous execution's k_msgvec
    sgemm_sk<0,0><<<dim3(4, 7, 8), 256, 0, 0>>>(roi,  w1, b1, p_h1, NNODE, HD1, IMGF, 256, nullptr);
    sgemm_sk<1,0><<<dim3(2, 7, 8), 256, 0, 0>>>(p_h1, w2, b2, p_h2, NNODE, HD2, HD1, 64, nullptr);
    sgemm_sk<1,0><<<dim3(8, 7, 4), 256, 0, 0>>>(p_h2, w3, b3, p_x,  NNODE, NCH, HD2, 64, nullptr);
    // g4 also zeroes out[0..800) for k_msgvec's atomics
    sgemm_sk<0,1><<<dim3(4, 7, 8), 256, 0, 0>>>(p_x, wp2, (const float*)nullptr, p_M,
                                                NNODE, 512, NCH, 128, out);

    // join: merged msg + vec + scratch re-zero
    cudaStreamWaitEvent(0, ev2, 0);
    k_msgvec<<<NNODE, 256, 0, 0>>>(out + 1600, p_M, p_x, p_h1,
                                   wi, bi, bp2, rw, rb, wp1, bp1,
                                   out + 800, out);
}

// round 13
// speedup vs baseline: 1.4916x; 1.3326x over previous
#include <cuda_runtime.h>
#include <cuda_fp16.h>
#include <math.h>

typedef unsigned long long ull;
typedef unsigned int uint;

// ---------------- problem constants ----------------
#define NNODE 200
#define IMGF  2048
#define HD1   512
#define HD2   256
#define NCH   1024
#define NEDGE 39800
#define TE    64          // edges per block (4 m-tiles of 16)
#define EBLK  622         // ceil(39800/64)

// ---------------- f32x2 helpers ----------------
__device__ __forceinline__ ull pack2(float a) {
    ull r; asm("mov.b64 %0,{%1,%1};" : "=l"(r) : "f"(a)); return r;
}
__device__ __forceinline__ void ffma2(ull& acc, ull a, ull b) {
    asm("fma.rn.f32x2 %0,%1,%2,%0;" : "+l"(acc) : "l"(a), "l"(b));
}
__device__ __forceinline__ float2 unpk(ull v) {
    float2 r; asm("mov.b64 {%0,%1},%2;" : "=f"(r.x), "=f"(r.y) : "l"(v)); return r;
}

// ---------------- device scratch ----------------
// h1,h2,x,M are re-zeroed by k_msgvec at the END of every execution
// (device globals start zero-initialized, invariant holds across replays).
#define OFF_H1   0
#define OFF_H2   (OFF_H1 + NNODE*HD1)
#define OFF_X    (OFF_H2 + NNODE*HD2)
#define OFF_M    (OFF_X  + NNODE*NCH)
#define OFF_P    (OFF_M  + NNODE*512)
#define OFF_Q    (OFF_P + NNODE*256)
#define SCR_TOTAL (OFF_Q + NNODE*256)
__device__ float g_scr[SCR_TOTAL];
__device__ __half g_wt[64 * 256];       // we2^T in fp16: [n][k]

__device__ __forceinline__ uint smem_u32(const void* p) {
    uint a;
    asm("{ .reg .u64 t; cvta.to.shared.u64 t, %1; cvt.u32.u64 %0, t; }"
        : "=r"(a) : "l"(p));
    return a;
}

// P/Q precompute + we2^T fp16 conversion (designated blocks)
__global__ void k_pq(const float* __restrict__ bbox, const float* __restrict__ dirs,
                     const float* __restrict__ we1, const float* __restrict__ we2,
                     float* __restrict__ P, float* __restrict__ Q) {
    __shared__ float a[8];
    int n = blockIdx.y, j = blockIdx.x * 128 + threadIdx.x;
    if (threadIdx.x < 8) {
        int c = threadIdx.x;
        a[c] = (c < 4) ? bbox[n * 4 + c] * (1.0f / 1024.0f) : dirs[n * 4 + c - 4];
    }
    // we2^T -> g_wt (fp16): blocks (x==0, y<8), each thread 16 elems
    if (blockIdx.x == 0 && blockIdx.y < 8) {
        int base = (blockIdx.y * 128 + threadIdx.x) * 16;
        #pragma unroll
        for (int i = 0; i < 16; ++i) {
            int m = base + i;
            int nn = m >> 8, k = m & 255;
            g_wt[m] = __float2half(we2[k * 64 + nn]);
        }
    }
    __syncthreads();
    float p = 0.f, q = 0.f;
    #pragma unroll
    for (int c = 0; c < 8; ++c) {
        p += a[c] * we1[c * 256 + j];
        q += a[c] * we1[(c + 8) * 256 + j];
    }
    P[n * 256 + j] = p;
    Q[n * 256 + j] = q;
}

// ---------------- split-K SGEMM: atomicAdd(C, A@B), split 0 adds bias --------
template <int RELU_A, int TRB>
__global__ void __launch_bounds__(256) sgemm_sk(
    const float* __restrict__ A, const float* __restrict__ B,
    const float* __restrict__ bias, float* __restrict__ C,
    int M, int N, int K, int Ks, float* __restrict__ zout) {
    __shared__ float sA[16][36];
    __shared__ float sB[16][132];
    const int tid = threadIdx.x;
    const int tx = tid & 31, ty = tid >> 5;
    const int m0 = blockIdx.y * 32, n0 = blockIdx.x * 128;
    const int kbeg = blockIdx.z * Ks;

    if (zout != nullptr && blockIdx.y == 0 && blockIdx.z == 0) {
        int idx = blockIdx.x * 256 + tid;
        if (idx < 2 * NNODE * 4) zout[idx] = 0.f;
    }

    ull acc[8];
    #pragma unroll
    for (int i = 0; i < 8; ++i) acc[i] = 0ULL;

    for (int k0 = kbeg; k0 < kbeg + Ks; k0 += 16) {
        {
            int m = tid >> 3, kq = (tid & 7) * 2;
            float2 a = make_float2(0.f, 0.f);
            if (m0 + m < M) a = *(const float2*)(A + (size_t)(m0 + m) * K + k0 + kq);
            if (RELU_A) { a.x = fmaxf(a.x, 0.f); a.y = fmaxf(a.y, 0.f); }
            sA[kq][m] = a.x; sA[kq + 1][m] = a.y;
        }
        if (TRB == 0) {
            int k = tid >> 4, n8 = (tid & 15) * 8;
            const float* bp = B + (size_t)(k0 + k) * N + n0 + n8;
            float4 b0 = *(const float4*)(bp);
            float4 b1 = *(const float4*)(bp + 4);
            *(float4*)&sB[k][n8] = b0;
            *(float4*)&sB[k][n8 + 4] = b1;
        } else {
            int k = tid & 15, n8 = (tid >> 4) * 8;
            int i = k0 + k, j0 = n0 + n8;
            const float* bp = B + (size_t)(j0 >> 2) * 4096 + i * 4;
            float4 b0 = *(const float4*)(bp);
            float4 b1 = *(const float4*)(bp + 4096);
            *(float4*)&sB[k][n8] = b0;
            *(float4*)&sB[k][n8 + 4] = b1;
        }
        __syncthreads();
        #pragma unroll
        for (int k = 0; k < 16; ++k) {
            float4 av = *(const float4*)&sA[k][ty * 4];
            ulonglong2 bv = *(const ulonglong2*)&sB[k][tx * 4];
            ull a0 = pack2(av.x), a1 = pack2(av.y), a2 = pack2(av.z), a3 = pack2(av.w);
            ffma2(acc[0], a0, bv.x); ffma2(acc[1], a0, bv.y);
            ffma2(acc[2], a1, bv.x); ffma2(acc[3], a1, bv.y);
            ffma2(acc[4], a2, bv.x); ffma2(acc[5], a2, bv.y);
            ffma2(acc[6], a3, bv.x); ffma2(acc[7], a3, bv.y);
        }
        __syncthreads();
    }
    const bool addb = (bias != nullptr) && (blockIdx.z == 0);
    #pragma unroll
    for (int r = 0; r < 4; ++r) {
        int row = m0 + ty * 4 + r;
        if (row >= M) continue;
        float2 v01 = unpk(acc[r * 2]), v23 = unpk(acc[r * 2 + 1]);
        float v[4] = {v01.x, v01.y, v23.x, v23.y};
        int col = n0 + tx * 4;
        #pragma unroll
        for (int j = 0; j < 4; ++j) {
            float o = v[j];
            if (addb) o += bias[col + j];
            atomicAdd(&C[(size_t)row * N + col + j], o);
        }
    }
}

// ---------------- edge MLP with HMMA phase-2 ----------------
// dyn smem: s_wt half[64*264] | s_h1 half[64*264]
__global__ void __launch_bounds__(128) k_edge_mlp(
    const float* __restrict__ P, const float* __restrict__ Q,
    const float* __restrict__ pri,
    const float* __restrict__ be1,
    const float* __restrict__ be2,
    const float* __restrict__ we3, const float* __restrict__ be3,
    float* __restrict__ out_ea) {
    extern __shared__ __half s_dyn[];
    __half* s_wt = s_dyn;                 // [n][k] stride 264
    __half* s_h1 = s_dyn + 64 * 264;      // [e][k] stride 264
    __shared__ float s_h2[TE][68];
    __shared__ float s_ea[TE][4];
    __shared__ int s_src[TE], s_dst[TE];

    const int t = threadIdx.x;
    const int e0 = blockIdx.x * TE;
    const int wid = t >> 5, lane = t & 31;

    if (t < TE) {
        int e = e0 + t;
        if (e >= NEDGE) e = NEDGE - 1;
        int i = e / 199;
        int r = e - i * 199;
        int j = (r < i) ? r : (r + 1);
        s_src[t] = i; s_dst[t] = j;
    }
    // stage we2^T fp16 into smem (stride 264): 2048 int4 chunks / 128 thr
    {
        const int4* src = (const int4*)g_wt;
        #pragma unroll
        for (int i = 0; i < 16; ++i) {
            int c = i * 128 + t;          // 0..2047
            int n = c >> 5, kc = c & 31;  // row, int4-chunk (8 halfs)
            *(int4*)(s_wt + n * 264 + kc * 8) = src[c];
        }
    }
    __syncthreads();

    // phase 1: h1 = relu(P[src] + Q[dst] + be1) -> fp16 smem
    #pragma unroll
    for (int l = 0; l < 32; ++l) {
        int idx = l * 128 + t;            // 64 edges x 64 float4 groups
        int el = idx >> 6, j4 = idx & 63;
        float4 p = ((const float4*)(P + s_src[el] * 256))[j4];
        float4 q = ((const float4*)(Q + s_dst[el] * 256))[j4];
        float4 b = ((const float4*)be1)[j4];
        __half2 h0 = __floats2half2_rn(fmaxf(p.x + q.x + b.x, 0.f),
                                       fmaxf(p.y + q.y + b.y, 0.f));
        __half2 h1 = __floats2half2_rn(fmaxf(p.z + q.z + b.z, 0.f),
                                       fmaxf(p.w + q.w + b.w, 0.f));
        __half2* dst = (__half2*)(s_h1 + el * 264 + j4 * 4);
        dst[0] = h0; dst[1] = h1;
    }
    __syncthreads();

    // phase 2: [64 x 256] @ [256 x 64] via mma.m16n8k16 f16->f32
    {
        const uint sAb = smem_u32(s_h1);
        const uint sWb = smem_u32(s_wt);
        const int aj = lane & 7, ag = lane >> 3;
        const uint a_off = (uint)(((ag & 1) * 8 + aj) * 528 + (ag >> 1) * 16);
        const int bj = lane & 7, bg = (lane >> 3) & 1;

        float D[4][2][4];
        #pragma unroll
        for (int mt = 0; mt < 4; ++mt)
            #pragma unroll
            for (int nt = 0; nt < 2; ++nt)
                #pragma unroll
                for (int i = 0; i < 4; ++i) D[mt][nt][i] = 0.f;

        #pragma unroll 4
        for (int ks = 0; ks < 16; ++ks) {
            uint a[4][4];
            #pragma unroll
            for (int mt = 0; mt < 4; ++mt) {
                uint addr = sAb + (uint)(mt * 16 * 528 + ks * 32) + a_off;
                asm volatile("ldmatrix.sync.aligned.m8n8.x4.shared.b16 "
                             "{%0,%1,%2,%3}, [%4];"
                             : "=r"(a[mt][0]), "=r"(a[mt][1]),
                               "=r"(a[mt][2]), "=r"(a[mt][3]) : "r"(addr));
            }
            #pragma unroll
            for (int nt = 0; nt < 2; ++nt) {
                uint b0, b1;
                uint baddr = sWb + (uint)((wid * 16 + nt * 8 + bj) * 528
                                          + ks * 32 + bg * 16);
                asm volatile("ldmatrix.sync.aligned.m8n8.x2.shared.b16 "
                             "{%0,%1}, [%2];" : "=r"(b0), "=r"(b1) : "r"(baddr));
                #pragma unroll
                for (int mt = 0; mt < 4; ++mt) {
                    asm volatile(
                        "mma.sync.aligned.m16n8k16.row.col.f32.f16.f16.f32 "
                        "{%0,%1,%2,%3}, {%4,%5,%6,%7}, {%8,%9}, {%0,%1,%2,%3};"
                        : "+f"(D[mt][nt][0]), "+f"(D[mt][nt][1]),
                          "+f"(D[mt][nt][2]), "+f"(D[mt][nt][3])
                        : "r"(a[mt][0]), "r"(a[mt][1]), "r"(a[mt][2]), "r"(a[mt][3]),
                          "r"(b0), "r"(b1));
                }
            }
        }

        // epilogue: D -> s_h2 with bias + relu
        const int r = lane >> 2, c = (lane & 3) * 2;
        #pragma unroll
        for (int mt = 0; mt < 4; ++mt)
            #pragma unroll
            for (int nt = 0; nt < 2; ++nt) {
                int n = wid * 16 + nt * 8 + c;
                float bc0 = be2[n], bc1 = be2[n + 1];
                int e = mt * 16 + r;
                s_h2[e][n]     = fmaxf(D[mt][nt][0] + bc0, 0.f);
                s_h2[e][n + 1] = fmaxf(D[mt][nt][1] + bc1, 0.f);
                s_h2[e + 8][n]     = fmaxf(D[mt][nt][2] + bc0, 0.f);
                s_h2[e + 8][n + 1] = fmaxf(D[mt][nt][3] + bc1, 0.f);
            }
    }
    __syncthreads();

    // phase 3: L3 64->3 + sigmoid — 192 jobs over 128 threads (FIX: strided)
    for (int idx = t; idx < 192; idx += 128) {
        int e = idx / 3, c = idx - (idx / 3) * 3;
        float s = be3[c];
        #pragma unroll 8
        for (int k = 0; k < 64; ++k) s += s_h2[e][k] * we3[k * 3 + c];
        s_ea[e][c] = 1.f / (1.f + __expf(-s));
    }
    if (t < TE) s_ea[t][3] = (pri[s_src[t]] > pri[s_dst[t]]) ? 1.f : 0.f;
    __syncthreads();

    #pragma unroll
    for (int l = 0; l < 2; ++l) {
        int idx = l * 128 + t;            // 64 edges x 4
        int e = idx >> 2, c = idx & 3;
        if (e0 + e < NEDGE) out_ea[(size_t)(e0 + e) * 4 + c] = s_ea[e][c];
    }
}

// -------- merged msg + vec + scratch-rezero: one block per src node ----------
__global__ void __launch_bounds__(256) k_msgvec(
    const float* __restrict__ ea, float* __restrict__ Mn,
    float* __restrict__ x, float* __restrict__ h12,
    const float* __restrict__ wi, const float* __restrict__ bi,
    const float* __restrict__ bp2,
    const float* __restrict__ rw, const float* __restrict__ rb,
    const float* __restrict__ wp1, const float* __restrict__ bp1,
    float* __restrict__ out_expl, float* __restrict__ out_agg) {
    __shared__ float sM[512];
    __shared__ float swp[512];
    __shared__ float sbp[128];
    __shared__ float red[8][13];
    __shared__ float s_cv[4];
    const int src = blockIdx.x, t = threadIdx.x;
    const float4 z4 = make_float4(0.f, 0.f, 0.f, 0.f);

    sM[t] = Mn[src * 512 + t];
    sM[t + 256] = Mn[src * 512 + 256 + t];
    Mn[src * 512 + t] = 0.f;
    Mn[src * 512 + 256 + t] = 0.f;
    swp[t] = wp1[t]; swp[t + 256] = wp1[t + 256];
    if (t < 128) sbp[t] = bp1[t];

    float4 xv = *(const float4*)(x + (size_t)src * NCH + t * 4);
    *(float4*)(x + (size_t)src * NCH + t * 4) = z4;
    {
        float xa[4] = {xv.x, xv.y, xv.z, xv.w};
        float v[12];
        #pragma unroll
        for (int c = 0; c < 12; ++c) v[c] = 0.f;
        #pragma unroll
        for (int j = 0; j < 4; ++j) {
            int i = t * 4 + j;
            float xs = xa[j];
            float4 w0 = *(const float4*)(wi  + i * 4);
            float4 w1 = *(const float4*)(bp2 + i * 4);
            float4 w2 = *(const float4*)(rw  + i * 4);
            v[0] += xs * w0.x; v[1] += xs * w0.y; v[2]  += xs * w0.z; v[3]  += xs * w0.w;
            v[4] += xs * w1.x; v[5] += xs * w1.y; v[6]  += xs * w1.z; v[7]  += xs * w1.w;
            v[8] += xs * w2.x; v[9] += xs * w2.y; v[10] += xs * w2.z; v[11] += xs * w2.w;
        }
        #pragma unroll
        for (int s = 16; s; s >>= 1)
            #pragma unroll
            for (int c = 0; c < 12; ++c) v[c] += __shfl_xor_sync(0xffffffffu, v[c], s);
        if ((t & 31) == 0)
            #pragma unroll
            for (int c = 0; c < 12; ++c) red[t >> 5][c] = v[c];
    }
    if (t < 192) ((float4*)h12)[src * 192 + t] = z4;
    __syncthreads();
    if (t < 12) {
        float s = 0.f;
        #pragma unroll
        for (int w = 0; w < 8; ++w) s += red[w][t];
        int o = t & 3;
        if (t < 4)      out_expl[src * 4 + o] = 1.f / (1.f + __expf(-(s + bi[o])));
        else if (t < 8) s_cv[o] = s;
        else            atomicAdd(&out_agg[src * 4 + o], s + rb[o]);
    }
    __syncthreads();

    float4 cv = *(const float4*)s_cv;
    const int slot = t >> 2, q = t & 3;
    for (int eb = 0; eb < 4; ++eb) {
        int el = eb * 64 + slot;
        if (el >= 199) break;
        int dst = el + (el >= src ? 1 : 0);
        int e = src * 199 + el;
        float4 eav = ((const float4*)ea)[e];
        float4 a = make_float4(0.f, 0.f, 0.f, 0.f);
        #pragma unroll 8
        for (int kk = 0; kk < 32; ++kk) {
            int k = kk * 4 + q;
            float h = sbp[k] + eav.x * swp[k] + eav.y * swp[128 + k]
                             + eav.z * swp[256 + k] + eav.w * swp[384 + k];
            h = fmaxf(h, 0.f);
            float4 m = ((const float4*)sM)[k];
            a.x += h * m.x; a.y += h * m.y; a.z += h * m.z; a.w += h * m.w;
        }
        #pragma unroll
        for (int s = 1; s < 4; s <<= 1) {
            a.x += __shfl_xor_sync(0xffffffffu, a.x, s);
            a.y += __shfl_xor_sync(0xffffffffu, a.y, s);
            a.z += __shfl_xor_sync(0xffffffffu, a.z, s);
            a.w += __shfl_xor_sync(0xffffffffu, a.w, s);
        }
        if (q == 0) {
            atomicAdd(&out_agg[dst * 4 + 0], a.x + cv.x);
            atomicAdd(&out_agg[dst * 4 + 1], a.y + cv.y);
            atomicAdd(&out_agg[dst * 4 + 2], a.z + cv.z);
            atomicAdd(&out_agg[dst * 4 + 3], a.w + cv.w);
        }
    }
}

// ---------------- launch ----------------
extern "C" void kernel_launch(void* const* d_in, const int* in_sizes, int n_in,
                              void* d_out, int out_size) {
    const float* roi  = (const float*)d_in[0];
    const float* bbox = (const float*)d_in[1];
    const float* dir  = (const float*)d_in[2];
    const float* pri  = (const float*)d_in[3];
    const float* w1  = (const float*)d_in[4];  const float* b1  = (const float*)d_in[5];
    const float* w2  = (const float*)d_in[6];  const float* b2  = (const float*)d_in[7];
    const float* w3  = (const float*)d_in[8];  const float* b3  = (const float*)d_in[9];
    const float* wi  = (const float*)d_in[10]; const float* bi  = (const float*)d_in[11];
    const float* we1 = (const float*)d_in[12]; const float* be1 = (const float*)d_in[13];
    const float* we2 = (const float*)d_in[14]; const float* be2 = (const float*)d_in[15];
    const float* we3 = (const float*)d_in[16]; const float* be3 = (const float*)d_in[17];
    const float* wp1 = (const float*)d_in[18]; const float* bp1 = (const float*)d_in[19];
    const float* wp2 = (const float*)d_in[20]; const float* bp2 = (const float*)d_in[21];
    const float* rw  = (const float*)d_in[22]; const float* rb  = (const float*)d_in[23];
    float* out = (float*)d_out;

    float* scr;
    cudaGetSymbolAddress((void**)&scr, g_scr);
    float* p_h1 = scr + OFF_H1;
    float* p_h2 = scr + OFF_H2;
    float* p_x  = scr + OFF_X;
    float* p_M  = scr + OFF_M;
    float* p_P  = scr + OFF_P;
    float* p_Q  = scr + OFF_Q;

    static cudaStream_t s2 = nullptr;
    static cudaEvent_t evF = nullptr, ev2 = nullptr;
    if (!s2) {
        cudaStreamCreateWithFlags(&s2, cudaStreamNonBlocking);
        cudaEventCreateWithFlags(&evF, cudaEventDisableTiming);
        cudaEventCreateWithFlags(&ev2, cudaEventDisableTiming);
        cudaFuncSetAttribute(k_edge_mlp,
                             cudaFuncAttributeMaxDynamicSharedMemorySize,
                             2 * 64 * 264 * (int)sizeof(__half));
    }

    // fork edge branch
    cudaEventRecord(evF, 0);
    cudaStreamWaitEvent(s2, evF, 0);
    k_pq<<<dim3(2, NNODE), 128, 0, s2>>>(bbox, dir, we1, we2, p_P, p_Q);
    k_edge_mlp<<<EBLK, 128, 2 * 64 * 264 * sizeof(__half), s2>>>(
        p_P, p_Q, pri, be1, be2, we3, be3, out + 1600);
    cudaEventRecord(ev2, s2);

    // main chain (stream 0): scratch pre-zeroed by previous execution
    sgemm_sk<0,0><<<dim3(4, 7, 8), 256, 0, 0>>>(roi,  w1, b1, p_h1, NNODE, HD1, IMGF, 256, nullptr);
    sgemm_sk<1,0><<<dim3(2, 7, 8), 256, 0, 0>>>(p_h1, w2, b2, p_h2, NNODE, HD2, HD1, 64, nullptr);
    sgemm_sk<1,0><<<dim3(8, 7, 4), 256, 0, 0>>>(p_h2, w3, b3, p_x,  NNODE, NCH, HD2, 64, nullptr);
    sgemm_sk<0,1><<<dim3(4, 7, 8), 256, 0, 0>>>(p_x, wp2, (const float*)nullptr, p_M,
                                                NNODE, 512, NCH, 128, out);

    // join: merged msg + vec + scratch re-zero
    cudaStreamWaitEvent(0, ev2, 0);
    k_msgvec<<<NNODE, 256, 0, 0>>>(out + 1600, p_M, p_x, p_h1,
                                   wi, bi, bp2, rw, rb, wp1, bp1,
                                   out + 800, out);
}